// round 1
// baseline (speedup 1.0000x reference)
#include <cuda_runtime.h>
#include <math.h>

#define S_LEN 16384
#define DIM   1024
#define HID   1024
#define G4    4096   // 4*HID

// ---------------- scratch (no allocations allowed) ----------------
__device__ float g_xg[(size_t)S_LEN * G4];   // 256 MB: precomputed input gates
__device__ float g_hs[(size_t)S_LEN * HID];  // 64 MB: h_t for every step
__device__ float g_alpha[S_LEN];
__device__ unsigned g_bar_count;             // zero-init; returns to 0 every barrier
__device__ unsigned g_bar_gen;               // monotonically increasing (replay-safe)

// ---------------- helpers ----------------
__device__ __forceinline__ float fsigmoid(float x) {
    return __fdividef(1.0f, 1.0f + __expf(-x));
}
__device__ __forceinline__ float ftanh(float x) {
    float e = __expf(2.0f * x);
    return 1.0f - __fdividef(2.0f, e + 1.0f);
}

__device__ __forceinline__ void grid_bar(unsigned nb) {
    __threadfence();
    unsigned g = *(volatile unsigned*)&g_bar_gen;
    unsigned old = atomicAdd(&g_bar_count, 1u);
    if (old == nb - 1u) {
        atomicExch(&g_bar_count, 0u);
        __threadfence();
        atomicAdd(&g_bar_gen, 1u);
    } else {
        while (*(volatile unsigned*)&g_bar_gen == g) { }
        __threadfence();
    }
}

// ================= Phase 1: xg = inputs @ W_ih^T + (b_ih + b_hh) =================
// C[M=16384][N=4096], K=1024. A row-major [M,K], B row-major [N,K] (NT gemm).
__global__ void __launch_bounds__(256) gemm_kernel(
    const float* __restrict__ A, const float* __restrict__ B,
    const float* __restrict__ b1, const float* __restrict__ b2)
{
    __shared__ __align__(16) float As[16][132];
    __shared__ __align__(16) float Bs[16][132];
    const int tid = threadIdx.x;
    const int bx = blockIdx.x;       // 0..31  (N blocks)
    const int by = blockIdx.y;       // 0..127 (M blocks)
    const int tx = tid & 15, ty = tid >> 4;
    const int rowA = by * 128;
    const int rowB = bx * 128;

    float acc[8][8];
#pragma unroll
    for (int i = 0; i < 8; i++)
#pragma unroll
        for (int jj = 0; jj < 8; jj++) acc[i][jj] = 0.0f;

    for (int kt = 0; kt < DIM; kt += 16) {
#pragma unroll
        for (int s = 0; s < 2; s++) {
            int f = tid + 256 * s;
            int r = f >> 2;
            int kq = (f & 3) * 4;
            float4 va = *(const float4*)&A[(size_t)(rowA + r) * DIM + kt + kq];
            As[kq + 0][r] = va.x; As[kq + 1][r] = va.y;
            As[kq + 2][r] = va.z; As[kq + 3][r] = va.w;
            float4 vb = *(const float4*)&B[(size_t)(rowB + r) * DIM + kt + kq];
            Bs[kq + 0][r] = vb.x; Bs[kq + 1][r] = vb.y;
            Bs[kq + 2][r] = vb.z; Bs[kq + 3][r] = vb.w;
        }
        __syncthreads();
#pragma unroll
        for (int k = 0; k < 16; k++) {
            float ar[8], br[8];
            *(float4*)(ar)     = *(const float4*)&As[k][ty * 8];
            *(float4*)(ar + 4) = *(const float4*)&As[k][ty * 8 + 4];
            *(float4*)(br)     = *(const float4*)&Bs[k][tx * 8];
            *(float4*)(br + 4) = *(const float4*)&Bs[k][tx * 8 + 4];
#pragma unroll
            for (int i = 0; i < 8; i++)
#pragma unroll
                for (int jj = 0; jj < 8; jj++)
                    acc[i][jj] = fmaf(ar[i], br[jj], acc[i][jj]);
        }
        __syncthreads();
    }

    float bb[8];
#pragma unroll
    for (int jj = 0; jj < 8; jj++) {
        int col = rowB + tx * 8 + jj;
        bb[jj] = b1[col] + b2[col];
    }
#pragma unroll
    for (int i = 0; i < 8; i++) {
        int row = rowA + ty * 8 + i;
#pragma unroll
        for (int jj = 0; jj < 8; jj++)
            g_xg[(size_t)row * G4 + rowB + tx * 8 + jj] = acc[i][jj] + bb[jj];
    }
}

// ================= Phase 2: persistent LSTM, W_hh register-resident =================
// 128 CTAs x 256 threads (1 CTA/SM, all resident). Warp w of CTA b owns h-index
// j = b*8 + w and its 4 gate rows. lane l covers k = m*32 + l (conflict-free LDS).
__global__ void __launch_bounds__(256, 1) lstm_kernel(const float* __restrict__ Whh)
{
    __shared__ float4 sh4[HID / 4];
    float* sh = (float*)sh4;

    const int tid  = threadIdx.x;
    const int warp = tid >> 5;
    const int lane = tid & 31;
    const int j    = blockIdx.x * 8 + warp;
    const unsigned nb = gridDim.x;

    // preload this warp's 4 gate rows of W_hh into registers (128 regs/thread)
    float w0[32], w1[32], w2[32], w3[32];
#pragma unroll
    for (int m = 0; m < 32; m++) {
        int kk = m * 32 + lane;
        w0[m] = __ldg(&Whh[((size_t)(0 * HID + j)) * HID + kk]);
        w1[m] = __ldg(&Whh[((size_t)(1 * HID + j)) * HID + kk]);
        w2[m] = __ldg(&Whh[((size_t)(2 * HID + j)) * HID + kk]);
        w3[m] = __ldg(&Whh[((size_t)(3 * HID + j)) * HID + kk]);
    }

    for (int i = tid; i < HID; i += 256) sh[i] = 0.0f;   // h_{-1} = 0
    float c = 0.0f;
    __syncthreads();

    for (int t = 0; t < S_LEN; t++) {
        // prefetch the 4 xg gate values for this j (lanes 0..3)
        float xv = 0.0f;
        if (lane < 4) xv = __ldcg(&g_xg[(size_t)t * G4 + lane * HID + j]);

        float a0 = 0.f, a1 = 0.f, a2 = 0.f, a3 = 0.f;
#pragma unroll
        for (int m = 0; m < 32; m++) {
            float hv = sh[m * 32 + lane];
            a0 = fmaf(w0[m], hv, a0);
            a1 = fmaf(w1[m], hv, a1);
            a2 = fmaf(w2[m], hv, a2);
            a3 = fmaf(w3[m], hv, a3);
        }
#pragma unroll
        for (int off = 16; off; off >>= 1) {
            a0 += __shfl_xor_sync(0xffffffffu, a0, off);
            a1 += __shfl_xor_sync(0xffffffffu, a1, off);
            a2 += __shfl_xor_sync(0xffffffffu, a2, off);
            a3 += __shfl_xor_sync(0xffffffffu, a3, off);
        }
        float xi = __shfl_sync(0xffffffffu, xv, 0);
        float xf = __shfl_sync(0xffffffffu, xv, 1);
        float xc = __shfl_sync(0xffffffffu, xv, 2);
        float xo = __shfl_sync(0xffffffffu, xv, 3);

        if (lane == 0) {
            float gi = fsigmoid(a0 + xi);
            float gf = fsigmoid(a1 + xf);
            float gc = ftanh(a2 + xc);
            float go = fsigmoid(a3 + xo);
            c = gf * c + gi * gc;
            g_hs[(size_t)t * HID + j] = go * ftanh(c);
        }

        __syncthreads();                 // all warps done with old sh + stores issued
        if (tid == 0) grid_bar(nb);      // global publish of hs[t]
        __syncthreads();
        sh4[tid] = __ldcg(((const float4*)(g_hs + (size_t)t * HID)) + tid);
        __syncthreads();
    }
}

// ================= Phase 3: alpha = sigmoid(hs @ W_fc^T + b_fc) =================
__global__ void __launch_bounds__(256) alpha_kernel(const float* __restrict__ Wfc,
                                                    const float* __restrict__ bfc)
{
    const int lane = threadIdx.x & 31;
    const int t = blockIdx.x * 8 + (threadIdx.x >> 5);
    const float4* hp = (const float4*)(g_hs + (size_t)t * HID);
    const float4* wp = (const float4*)Wfc;
    float acc = 0.0f;
#pragma unroll
    for (int i = 0; i < 8; i++) {
        float4 h4 = __ldcg(hp + i * 32 + lane);
        float4 w4 = __ldg(wp + i * 32 + lane);
        acc += h4.x * w4.x + h4.y * w4.y + h4.z * w4.z + h4.w * w4.w;
    }
#pragma unroll
    for (int off = 16; off; off >>= 1)
        acc += __shfl_xor_sync(0xffffffffu, acc, off);
    if (lane == 0)
        g_alpha[t] = fsigmoid(acc + __ldg(bfc));
}

// ================= Phase 4: scalar gated recurrence + loss =================
// out layout: [0]=loss, [1..N]=y_seq, [1+N..1+2N)=a_seq, [1+2N..1+3N)=u,  N=16383
__global__ void __launch_bounds__(256) final_kernel(const float* __restrict__ up,
                                                    const float* __restrict__ tl,
                                                    float* __restrict__ out)
{
    const int N = S_LEN - 1;
    __shared__ float u_s[2048];
    __shared__ float al_s[2048];
    __shared__ int s_idx[256];
    const int tid = threadIdx.x;

    // first index where timing_label[i] > 0.8 (i in [0, N))
    int myidx = 0x7fffffff;
    for (int i = tid; i < N; i += 256)
        if (tl[i] > 0.8f && i < myidx) myidx = i;
    s_idx[tid] = myidx;
    __syncthreads();
    for (int off = 128; off; off >>= 1) {
        if (tid < off) s_idx[tid] = min(s_idx[tid], s_idx[tid + off]);
        __syncthreads();
    }
    const int idx = s_idx[0];
    const bool exists = (idx != 0x7fffffff);

    float a_pre = 0.f, y_pre = 0.f, u_at = 0.f, y_at = 0.f;
    for (int c0 = 0; c0 < N; c0 += 2048) {
        int cnt = min(2048, N - c0);
        for (int i = tid; i < cnt; i += 256) {
            u_s[i]  = 1.0f - up[c0 + i + 1];
            al_s[i] = g_alpha[c0 + i + 1];
        }
        __syncthreads();
        if (tid == 0) {
            for (int i = 0; i < cnt; i++) {
                float u  = u_s[i];
                float ai = al_s[i];
                float ag = u * a_pre + (1.0f - u) * ai;
                float y  = ag * u + (1.0f - ag) * y_pre;
                int gi = c0 + i;
                out[1 + gi]         = y;
                out[1 + N + gi]     = ag;
                out[1 + 2 * N + gi] = u;
                if (gi == idx) { u_at = u; y_at = y; }
                a_pre = ag; y_pre = y;
            }
        }
        __syncthreads();
    }
    if (tid == 0) {
        float ylast = y_pre;
        float loss;
        if (exists)
            loss = (u_at < 0.5f) ? 0.0f : (y_at - 0.8f) * (y_at - 0.8f);
        else
            loss = (ylast >= 0.8f) ? (ylast - 0.4f) * (ylast - 0.4f) : 0.0f;
        out[0] = loss;
    }
}

// ================= launch =================
extern "C" void kernel_launch(void* const* d_in, const int* in_sizes, int n_in,
                              void* d_out, int out_size)
{
    const float* inputs    = (const float*)d_in[0];
    const float* uttr_pred = (const float*)d_in[1];
    const float* timing    = (const float*)d_in[2];
    /* d_in[3] uttr_label unused */
    const float* W_ih = (const float*)d_in[4];
    const float* W_hh = (const float*)d_in[5];
    const float* b_ih = (const float*)d_in[6];
    const float* b_hh = (const float*)d_in[7];
    const float* W_fc = (const float*)d_in[8];
    const float* b_fc = (const float*)d_in[9];
    float* out = (float*)d_out;

    dim3 ggrid(32, 128);
    gemm_kernel<<<ggrid, 256>>>(inputs, W_ih, b_ih, b_hh);
    lstm_kernel<<<128, 256>>>(W_hh);
    alpha_kernel<<<S_LEN / 8, 256>>>(W_fc, b_fc);
    final_kernel<<<1, 256>>>(uttr_pred, timing, out);
}

// round 2
// speedup vs baseline: 1.5502x; 1.5502x over previous
#include <cuda_runtime.h>
#include <math.h>

#define S_LEN 16384
#define DIM   1024
#define HID   1024
#define G4    4096   // 4*HID

// ---------------- scratch (no allocations allowed) ----------------
__device__ float g_xg[(size_t)S_LEN * G4];                  // 256 MB: input gates
__device__ unsigned long long g_hpub[(size_t)S_LEN * HID];  // 128 MB: (tag<<32)|h
__device__ float g_alpha[S_LEN];
__device__ unsigned g_epoch;                                // bumped once per launch

// ---------------- helpers ----------------
__device__ __forceinline__ float fsigmoid(float x) {
    return __fdividef(1.0f, 1.0f + __expf(-x));
}
__device__ __forceinline__ float ftanh(float x) {
    float e = __expf(2.0f * x);
    return 1.0f - __fdividef(2.0f, e + 1.0f);
}
__device__ __forceinline__ unsigned long long fma2(unsigned long long a,
                                                   unsigned long long b,
                                                   unsigned long long c) {
    unsigned long long d;
    asm("fma.rn.f32x2 %0, %1, %2, %3;" : "=l"(d) : "l"(a), "l"(b), "l"(c));
    return d;
}
__device__ __forceinline__ unsigned long long packf2(float x, float y) {
    return (unsigned long long)__float_as_uint(x) |
           ((unsigned long long)__float_as_uint(y) << 32);
}
__device__ __forceinline__ float lo_f(unsigned long long v) {
    return __uint_as_float((unsigned)v);
}
__device__ __forceinline__ float hi_f(unsigned long long v) {
    return __uint_as_float((unsigned)(v >> 32));
}

// ================= Phase 1: xg = inputs @ W_ih^T + (b_ih + b_hh) =================
__global__ void __launch_bounds__(256) gemm_kernel(
    const float* __restrict__ A, const float* __restrict__ B,
    const float* __restrict__ b1, const float* __restrict__ b2)
{
    __shared__ __align__(16) float As[16][132];
    __shared__ __align__(16) float Bs[16][132];
    const int tid = threadIdx.x;
    const int bx = blockIdx.x;       // 0..31  (N blocks)
    const int by = blockIdx.y;       // 0..127 (M blocks)
    const int tx = tid & 15, ty = tid >> 4;
    const int rowA = by * 128;
    const int rowB = bx * 128;

    float acc[8][8];
#pragma unroll
    for (int i = 0; i < 8; i++)
#pragma unroll
        for (int jj = 0; jj < 8; jj++) acc[i][jj] = 0.0f;

    for (int kt = 0; kt < DIM; kt += 16) {
#pragma unroll
        for (int s = 0; s < 2; s++) {
            int f = tid + 256 * s;
            int r = f >> 2;
            int kq = (f & 3) * 4;
            float4 va = *(const float4*)&A[(size_t)(rowA + r) * DIM + kt + kq];
            As[kq + 0][r] = va.x; As[kq + 1][r] = va.y;
            As[kq + 2][r] = va.z; As[kq + 3][r] = va.w;
            float4 vb = *(const float4*)&B[(size_t)(rowB + r) * DIM + kt + kq];
            Bs[kq + 0][r] = vb.x; Bs[kq + 1][r] = vb.y;
            Bs[kq + 2][r] = vb.z; Bs[kq + 3][r] = vb.w;
        }
        __syncthreads();
#pragma unroll
        for (int k = 0; k < 16; k++) {
            float ar[8], br[8];
            *(float4*)(ar)     = *(const float4*)&As[k][ty * 8];
            *(float4*)(ar + 4) = *(const float4*)&As[k][ty * 8 + 4];
            *(float4*)(br)     = *(const float4*)&Bs[k][tx * 8];
            *(float4*)(br + 4) = *(const float4*)&Bs[k][tx * 8 + 4];
#pragma unroll
            for (int i = 0; i < 8; i++)
#pragma unroll
                for (int jj = 0; jj < 8; jj++)
                    acc[i][jj] = fmaf(ar[i], br[jj], acc[i][jj]);
        }
        __syncthreads();
    }

    float bb[8];
#pragma unroll
    for (int jj = 0; jj < 8; jj++) {
        int col = rowB + tx * 8 + jj;
        bb[jj] = b1[col] + b2[col];
    }
#pragma unroll
    for (int i = 0; i < 8; i++) {
        int row = rowA + ty * 8 + i;
#pragma unroll
        for (int jj = 0; jj < 8; jj++)
            g_xg[(size_t)row * G4 + rowB + tx * 8 + jj] = acc[i][jj] + bb[jj];
    }
}

// ================= Phase 2: persistent LSTM, tagged-word dataflow sync =============
// 128 CTAs x 256 threads (1 CTA/SM). Warp w of CTA b owns h-index j = b*8 + w and
// its 4 gate rows. Lane l covers packed k-pairs {m*64+2l, m*64+2l+1}. No grid
// barrier: h values published as (tag|value) 64-bit words; consumers poll tags.
__global__ void __launch_bounds__(256, 1) lstm_kernel(const float* __restrict__ Whh)
{
    __shared__ __align__(16) float sh[HID];

    const int tid  = threadIdx.x;
    const int warp = tid >> 5;
    const int lane = tid & 31;
    const int j    = blockIdx.x * 8 + warp;
    const unsigned tagbase = (*(volatile unsigned*)&g_epoch) * (unsigned)S_LEN;

    // preload this warp's 4 gate rows of W_hh as packed f32x2 (128 regs/thread)
    unsigned long long W0[16], W1[16], W2[16], W3[16];
#pragma unroll
    for (int m = 0; m < 16; m++) {
        int kk = m * 64 + 2 * lane;
        float2 v0 = __ldg((const float2*)&Whh[((size_t)(0 * HID + j)) * HID + kk]);
        float2 v1 = __ldg((const float2*)&Whh[((size_t)(1 * HID + j)) * HID + kk]);
        float2 v2 = __ldg((const float2*)&Whh[((size_t)(2 * HID + j)) * HID + kk]);
        float2 v3 = __ldg((const float2*)&Whh[((size_t)(3 * HID + j)) * HID + kk]);
        W0[m] = packf2(v0.x, v0.y);
        W1[m] = packf2(v1.x, v1.y);
        W2[m] = packf2(v2.x, v2.y);
        W3[m] = packf2(v3.x, v3.y);
    }

    for (int i = tid; i < HID; i += 256) sh[i] = 0.0f;   // h_{-1} = 0
    float c = 0.0f;
    __syncthreads();

    for (int t = 0; t < S_LEN; t++) {
        // prefetch the 4 xg gate values for this j (lanes 0..3) — overlaps the poll
        float xv = 0.0f;
        if (lane < 4) xv = __ldcg(&g_xg[(size_t)t * G4 + lane * HID + j]);

        if (t > 0) {
            // consume h[t-1]: each thread polls 4 tagged words concurrently
            const unsigned want = tagbase + (unsigned)t;   // tag of step t-1
            volatile const unsigned long long* base = g_hpub + (size_t)(t - 1) * HID;
            unsigned long long v0, v1, v2, v3;
            for (;;) {
                v0 = base[tid];
                v1 = base[tid + 256];
                v2 = base[tid + 512];
                v3 = base[tid + 768];
                if ((unsigned)(v0 >> 32) == want && (unsigned)(v1 >> 32) == want &&
                    (unsigned)(v2 >> 32) == want && (unsigned)(v3 >> 32) == want)
                    break;
            }
            sh[tid]       = lo_f(v0);
            sh[tid + 256] = lo_f(v1);
            sh[tid + 512] = lo_f(v2);
            sh[tid + 768] = lo_f(v3);
        }
        __syncthreads();

        unsigned long long a0 = 0ull, a1 = 0ull, a2 = 0ull, a3 = 0ull;
#pragma unroll
        for (int m = 0; m < 16; m++) {
            unsigned long long hv = *(const unsigned long long*)&sh[m * 64 + 2 * lane];
            a0 = fma2(W0[m], hv, a0);
            a1 = fma2(W1[m], hv, a1);
            a2 = fma2(W2[m], hv, a2);
            a3 = fma2(W3[m], hv, a3);
        }
        float s0 = lo_f(a0) + hi_f(a0);
        float s1 = lo_f(a1) + hi_f(a1);
        float s2 = lo_f(a2) + hi_f(a2);
        float s3 = lo_f(a3) + hi_f(a3);
#pragma unroll
        for (int off = 16; off; off >>= 1) {
            s0 += __shfl_xor_sync(0xffffffffu, s0, off);
            s1 += __shfl_xor_sync(0xffffffffu, s1, off);
            s2 += __shfl_xor_sync(0xffffffffu, s2, off);
            s3 += __shfl_xor_sync(0xffffffffu, s3, off);
        }
        float xi = __shfl_sync(0xffffffffu, xv, 0);
        float xf = __shfl_sync(0xffffffffu, xv, 1);
        float xc = __shfl_sync(0xffffffffu, xv, 2);
        float xo = __shfl_sync(0xffffffffu, xv, 3);

        if (lane == 0) {
            float gi = fsigmoid(s0 + xi);
            float gf = fsigmoid(s1 + xf);
            float gc = ftanh(s2 + xc);
            float go = fsigmoid(s3 + xo);
            c = gf * c + gi * gc;
            float h = go * ftanh(c);
            unsigned long long w =
                ((unsigned long long)(tagbase + (unsigned)t + 1u) << 32) |
                (unsigned long long)__float_as_uint(h);
            *((volatile unsigned long long*)(g_hpub + (size_t)t * HID + j)) = w;
        }
        __syncthreads();   // all warps done reading sh before next poll overwrites it
    }
}

// ================= Phase 3: alpha = sigmoid(h @ W_fc^T + b_fc) =================
__global__ void __launch_bounds__(256) alpha_kernel(const float* __restrict__ Wfc,
                                                    const float* __restrict__ bfc)
{
    const int lane = threadIdx.x & 31;
    const int t = blockIdx.x * 8 + (threadIdx.x >> 5);
    const unsigned long long* hp = g_hpub + (size_t)t * HID;
    float acc = 0.0f;
#pragma unroll
    for (int i = 0; i < 32; i++) {
        unsigned long long w = __ldcg(&hp[i * 32 + lane]);
        acc += lo_f(w) * __ldg(&Wfc[i * 32 + lane]);
    }
#pragma unroll
    for (int off = 16; off; off >>= 1)
        acc += __shfl_xor_sync(0xffffffffu, acc, off);
    if (lane == 0)
        g_alpha[t] = fsigmoid(acc + __ldg(bfc));
}

// ================= Phase 4: parallel scans for gated recurrence + loss ===========
// a_g_i = u_i*a_{i-1} + (1-u_i)*ain_i  -> affine map (A,B)=(u, (1-u)*ain)
// y_i   = a_g_i*u_i + (1-a_g_i)*y_{i-1} -> affine map (C,D)=(1-a_g, a_g*u)
// out layout: [0]=loss, [1..N]=y_seq, [1+N..1+2N)=a_seq, [1+2N..1+3N)=u,  N=16383
__global__ void __launch_bounds__(1024) final_kernel(const float* __restrict__ up,
                                                     const float* __restrict__ tl,
                                                     float* __restrict__ out)
{
    const int N = S_LEN - 1;
    __shared__ float sA[1024], sB[1024];
    __shared__ int s_idx;
    const int tid = threadIdx.x;
    const int base = tid * 16;

    if (tid == 0) s_idx = 0x7fffffff;
    __syncthreads();
    // first index with timing_label[i] > 0.8 (i in [0, N))
    {
        int my = 0x7fffffff;
#pragma unroll
        for (int k = 0; k < 16; k++) {
            int i = base + k;
            if (i < N && tl[i] > 0.8f) { my = i; break; }
        }
        if (my != 0x7fffffff) atomicMin(&s_idx, my);
    }

    // ---- Phase A: local compose of (A,B) over 16 elems
    float A = 1.f, B = 0.f;
#pragma unroll
    for (int k = 0; k < 16; k++) {
        int i = base + k;
        float u  = (i < N) ? 1.0f - up[i + 1] : 1.0f;
        float ai = (i < N) ? g_alpha[i + 1]   : 0.0f;
        float Ak = u, Bk = (1.0f - u) * ai;
        B = Ak * B + Bk;
        A = Ak * A;
    }
    sA[tid] = A; sB[tid] = B;
    __syncthreads();
    // inclusive Hillis-Steele scan of affine composition
    for (int off = 1; off < 1024; off <<= 1) {
        float aL = 0.f, bL = 0.f;
        if (tid >= off) { aL = sA[tid - off]; bL = sB[tid - off]; }
        float aC = sA[tid], bC = sB[tid];
        __syncthreads();
        if (tid >= off) { sA[tid] = aC * aL; sB[tid] = aC * bL + bC; }
        __syncthreads();
    }
    const float a_prev0 = (tid == 0) ? 0.f : sB[tid - 1];   // applied to a_init=0
    __syncthreads();

    // ---- Phase C: recompute a_g per elem, emit a_seq/u, compose (C,D)
    float C = 1.f, D = 0.f;
    {
        float ap = a_prev0;
#pragma unroll
        for (int k = 0; k < 16; k++) {
            int i = base + k;
            float u  = (i < N) ? 1.0f - up[i + 1] : 1.0f;
            float ai = (i < N) ? g_alpha[i + 1]   : 0.0f;
            float ag = u * ap + (1.0f - u) * ai;
            ap = ag;
            if (i < N) {
                out[1 + N + i]     = ag;
                out[1 + 2 * N + i] = u;
                float Ck = 1.0f - ag, Dk = ag * u;
                D = Ck * D + Dk;
                C = Ck * C;
            }
        }
    }
    sA[tid] = C; sB[tid] = D;
    __syncthreads();
    for (int off = 1; off < 1024; off <<= 1) {
        float aL = 0.f, bL = 0.f;
        if (tid >= off) { aL = sA[tid - off]; bL = sB[tid - off]; }
        float aC = sA[tid], bC = sB[tid];
        __syncthreads();
        if (tid >= off) { sA[tid] = aC * aL; sB[tid] = aC * bL + bC; }
        __syncthreads();
    }
    const float y_prev0 = (tid == 0) ? 0.f : sB[tid - 1];

    // ---- Phase E: recompute a_g + y, emit y_seq
    {
        float ap = a_prev0, yp = y_prev0;
#pragma unroll
        for (int k = 0; k < 16; k++) {
            int i = base + k;
            float u  = (i < N) ? 1.0f - up[i + 1] : 1.0f;
            float ai = (i < N) ? g_alpha[i + 1]   : 0.0f;
            float ag = u * ap + (1.0f - u) * ai;
            ap = ag;
            if (i < N) {
                float y = ag * u + (1.0f - ag) * yp;
                yp = y;
                out[1 + i] = y;
            }
        }
    }
    __syncthreads();

    if (tid == 0) {
        int idx = s_idx;
        bool exists = (idx != 0x7fffffff);
        float loss;
        if (exists) {
            float u_at = 1.0f - up[idx + 1];
            float y_at = out[1 + idx];
            loss = (u_at < 0.5f) ? 0.0f : (y_at - 0.8f) * (y_at - 0.8f);
        } else {
            float yl = out[1 + N - 1];
            loss = (yl >= 0.8f) ? (yl - 0.4f) * (yl - 0.4f) : 0.0f;
        }
        out[0] = loss;
    }
}

// ================= epoch bump (replay-safe monotone tags) =================
__global__ void bump_kernel() { g_epoch = g_epoch + 1u; }

// ================= launch =================
extern "C" void kernel_launch(void* const* d_in, const int* in_sizes, int n_in,
                              void* d_out, int out_size)
{
    const float* inputs    = (const float*)d_in[0];
    const float* uttr_pred = (const float*)d_in[1];
    const float* timing    = (const float*)d_in[2];
    /* d_in[3] uttr_label unused */
    const float* W_ih = (const float*)d_in[4];
    const float* W_hh = (const float*)d_in[5];
    const float* b_ih = (const float*)d_in[6];
    const float* b_hh = (const float*)d_in[7];
    const float* W_fc = (const float*)d_in[8];
    const float* b_fc = (const float*)d_in[9];
    float* out = (float*)d_out;

    dim3 ggrid(32, 128);
    gemm_kernel<<<ggrid, 256>>>(inputs, W_ih, b_ih, b_hh);
    lstm_kernel<<<128, 256>>>(W_hh);
    alpha_kernel<<<S_LEN / 8, 256>>>(W_fc, b_fc);
    final_kernel<<<1, 1024>>>(uttr_pred, timing, out);
    bump_kernel<<<1, 1>>>();
}